// round 6
// baseline (speedup 1.0000x reference)
#include <cuda_runtime.h>
#include <float.h>

// GraphPooling: B=16, N=4096, F=8, H=64, C=256
// out[b,c,:,:] = sum_{n: seg[n]==c} softmax_w(b,n) * x[b,n,:,:]
// score[b,n] = (sum_e x[b,n,e] * W[h(e)]) / F + bias ; softmax per (b, segment).
// One warp per (b,c) item; no max-subtraction (scores bounded ~|1.6| << 88,
// exp(s)/sum exp(s) == exp(s-m)/sum exp(s-m) exactly in real arithmetic).

#define BB   16
#define NN   4096
#define FF   8
#define HH   64
#define CC   256
#define ROW  512
#define MAXPER 96
#define WPB  8           // warps per pool block

__device__ int g_list[CC * MAXPER];
__device__ int g_cnt[CC];

// Block c compacts segment c. Thread t owns chunk [t*32, t*32+32):
// concatenated order = increasing node index (deterministic).
__global__ __launch_bounds__(128) void build_lists_kernel(const int* __restrict__ seg) {
    __shared__ int s_seg[NN];
    __shared__ int s_cnt[128];
    __shared__ int s_wtot[4];

    const int c    = blockIdx.x;
    const int tid  = threadIdx.x;
    const int lane = tid & 31;
    const int wid  = tid >> 5;

    for (int i = tid; i < NN / 4; i += 128)
        ((int4*)s_seg)[i] = ((const int4*)seg)[i];
    __syncthreads();

    const int base = tid * 32;
    int cnt = 0;
    #pragma unroll
    for (int j = 0; j < 32; ++j) cnt += (s_seg[base + j] == c);

    int incl = cnt;
    #pragma unroll
    for (int off = 1; off < 32; off <<= 1) {
        const int v = __shfl_up_sync(0xFFFFFFFFu, incl, off);
        if (lane >= off) incl += v;
    }
    if (lane == 31) s_wtot[wid] = incl;
    s_cnt[tid] = incl - cnt;
    __syncthreads();
    int wbase = 0;
    #pragma unroll
    for (int w = 0; w < 4; ++w) { if (w < wid) wbase += s_wtot[w]; }
    const int offset = s_cnt[tid] + wbase;

    if (tid == 127) {
        const int total = offset + cnt;
        g_cnt[c] = total < MAXPER ? total : MAXPER;
    }

    int p = offset;
    #pragma unroll
    for (int j = 0; j < 32; ++j) {
        if (s_seg[base + j] == c) {
            if (p < MAXPER) g_list[c * MAXPER + p] = base + j;
            ++p;
        }
    }
}

// 512 blocks x 256 threads; warp handles item = wid*512 + blockIdx.x.
// b = item & 15, c = item >> 4. Lane owns float4 slots {lane, lane+32, lane+64, lane+96}.
__global__ __launch_bounds__(256) void pool_kernel(
    const float* __restrict__ x,
    const float* __restrict__ W,
    const float* __restrict__ bias,
    float* __restrict__ out)
{
    __shared__ int s_list[WPB][MAXPER];   // warp-private rows

    const int tid  = threadIdx.x;
    const int wid  = tid >> 5;
    const int lane = tid & 31;
    const int item = wid * 512 + blockIdx.x;   // [0, 4096)
    const int b    = item & 15;
    const int c    = item >> 4;

    const int cnt = g_cnt[c];
    int* myl = s_list[wid];
    for (int i = lane; i < cnt; i += 32) myl[i] = g_list[c * MAXPER + i];
    __syncwarp();

    // W tile: h((4p)&63) identical for slots p, p+32, p+64, p+96
    const float4 wv = *(const float4*)(W + ((lane * 4) & 63));
    const float  bv = __ldg(bias);
    const float* xb = x + (size_t)b * NN * ROW;

    float4 a0 = make_float4(0.f, 0.f, 0.f, 0.f), a1 = a0, a2 = a0, a3 = a0;
    float  d = 0.f;

    if (cnt > 0) {
        const float4* r = (const float4*)(xb + (size_t)myl[0] * ROW);
        float4 c0 = __ldg(r + lane),      c1 = __ldg(r + lane + 32),
               c2 = __ldg(r + lane + 64), c3 = __ldg(r + lane + 96);

        for (int i = 0; i < cnt; ++i) {
            // prefetch next row
            float4 n0 = c0, n1 = c1, n2 = c2, n3 = c3;
            if (i + 1 < cnt) {
                const float4* rn = (const float4*)(xb + (size_t)myl[i + 1] * ROW);
                n0 = __ldg(rn + lane);      n1 = __ldg(rn + lane + 32);
                n2 = __ldg(rn + lane + 64); n3 = __ldg(rn + lane + 96);
            }

            // score (warp reduce)
            float p = c0.x * wv.x + c0.y * wv.y + c0.z * wv.z + c0.w * wv.w;
            p      += c1.x * wv.x + c1.y * wv.y + c1.z * wv.z + c1.w * wv.w;
            p      += c2.x * wv.x + c2.y * wv.y + c2.z * wv.z + c2.w * wv.w;
            p      += c3.x * wv.x + c3.y * wv.y + c3.z * wv.z + c3.w * wv.w;
            #pragma unroll
            for (int off = 16; off; off >>= 1)
                p += __shfl_xor_sync(0xFFFFFFFFu, p, off);

            const float e = __expf(p * 0.125f + bv);   // |arg| <~ 2: safe, no rescale
            d += e;
            a0.x = fmaf(e, c0.x, a0.x); a0.y = fmaf(e, c0.y, a0.y);
            a0.z = fmaf(e, c0.z, a0.z); a0.w = fmaf(e, c0.w, a0.w);
            a1.x = fmaf(e, c1.x, a1.x); a1.y = fmaf(e, c1.y, a1.y);
            a1.z = fmaf(e, c1.z, a1.z); a1.w = fmaf(e, c1.w, a1.w);
            a2.x = fmaf(e, c2.x, a2.x); a2.y = fmaf(e, c2.y, a2.y);
            a2.z = fmaf(e, c2.z, a2.z); a2.w = fmaf(e, c2.w, a2.w);
            a3.x = fmaf(e, c3.x, a3.x); a3.y = fmaf(e, c3.y, a3.y);
            a3.z = fmaf(e, c3.z, a3.z); a3.w = fmaf(e, c3.w, a3.w);

            c0 = n0; c1 = n1; c2 = n2; c3 = n3;
        }
    }

    const float inv = (cnt > 0) ? (1.f / d) : 0.f;
    a0.x *= inv; a0.y *= inv; a0.z *= inv; a0.w *= inv;
    a1.x *= inv; a1.y *= inv; a1.z *= inv; a1.w *= inv;
    a2.x *= inv; a2.y *= inv; a2.z *= inv; a2.w *= inv;
    a3.x *= inv; a3.y *= inv; a3.z *= inv; a3.w *= inv;

    float4* o = (float4*)out + (size_t)(b * CC + c) * (ROW / 4);
    o[lane]      = a0;
    o[lane + 32] = a1;
    o[lane + 64] = a2;
    o[lane + 96] = a3;
}

extern "C" void kernel_launch(void* const* d_in, const int* in_sizes, int n_in,
                              void* d_out, int out_size) {
    const float* x    = (const float*)d_in[0];
    const float* W    = (const float*)d_in[1];
    const float* bias = (const float*)d_in[2];
    const int*   seg  = (const int*)d_in[3];

    build_lists_kernel<<<CC, 128>>>(seg);
    pool_kernel<<<512, 256>>>(x, W, bias, (float*)d_out);
}

// round 7
// speedup vs baseline: 1.0688x; 1.0688x over previous
#include <cuda_runtime.h>
#include <float.h>

// GraphPooling: B=16, N=4096, F=8, H=64, C=256
// out[b,c,:,:] = sum_{n: seg[n]==c} softmax_w(b,n) * x[b,n,:,:]
// score[b,n] = (sum_e x[b,n,e] * W[h(e)]) / F + bias ; softmax per (b, segment).
// One 32-thread CTA per (b,c) item: warp-autonomous streaming loop, no barriers,
// imbalance absorbed by the CTA scheduler. No max-subtraction (|score| <~ 2 << 88;
// exp(s)/sum exp(s) == exp(s-m)/sum exp(s-m)).

#define BB   16
#define NN   4096
#define FF   8
#define HH   64
#define CC   256
#define ROW  512
#define MAXPER 96

__device__ int g_list[CC * MAXPER];
__device__ int g_cnt[CC];

// Block c compacts segment c. Thread t owns chunk [t*32, t*32+32):
// concatenated order = increasing node index (deterministic).
__global__ __launch_bounds__(128) void build_lists_kernel(const int* __restrict__ seg) {
    __shared__ int s_seg[NN];
    __shared__ int s_cnt[128];
    __shared__ int s_wtot[4];

    const int c    = blockIdx.x;
    const int tid  = threadIdx.x;
    const int lane = tid & 31;
    const int wid  = tid >> 5;

    for (int i = tid; i < NN / 4; i += 128)
        ((int4*)s_seg)[i] = ((const int4*)seg)[i];
    __syncthreads();

    const int base = tid * 32;
    int cnt = 0;
    #pragma unroll
    for (int j = 0; j < 32; ++j) cnt += (s_seg[base + j] == c);

    int incl = cnt;
    #pragma unroll
    for (int off = 1; off < 32; off <<= 1) {
        const int v = __shfl_up_sync(0xFFFFFFFFu, incl, off);
        if (lane >= off) incl += v;
    }
    if (lane == 31) s_wtot[wid] = incl;
    s_cnt[tid] = incl - cnt;
    __syncthreads();
    int wbase = 0;
    #pragma unroll
    for (int w = 0; w < 4; ++w) { if (w < wid) wbase += s_wtot[w]; }
    const int offset = s_cnt[tid] + wbase;

    if (tid == 127) {
        const int total = offset + cnt;
        g_cnt[c] = total < MAXPER ? total : MAXPER;
    }

    int p = offset;
    #pragma unroll
    for (int j = 0; j < 32; ++j) {
        if (s_seg[base + j] == c) {
            if (p < MAXPER) g_list[c * MAXPER + p] = base + j;
            ++p;
        }
    }
}

// 4096 CTAs x 32 threads. CTA handles item = blockIdx.x: b = item & 15, c = item >> 4.
// Lane owns row float4 slots {lane, lane+32, lane+64, lane+96}.
__global__ __launch_bounds__(32) void pool_kernel(
    const float* __restrict__ x,
    const float* __restrict__ W,
    const float* __restrict__ bias,
    float* __restrict__ out)
{
    __shared__ int s_list[MAXPER];

    const int lane = threadIdx.x;
    const int item = blockIdx.x;
    const int b    = item & 15;
    const int c    = item >> 4;

    const int cnt = g_cnt[c];
    for (int i = lane; i < cnt; i += 32) s_list[i] = g_list[c * MAXPER + i];
    __syncwarp();

    // W tile: h((4p)&63) identical for slots p, p+32, p+64, p+96
    const float4 wv = *(const float4*)(W + ((lane * 4) & 63));
    const float  bv = __ldg(bias);
    const float* xb = x + (size_t)b * NN * ROW;

    float4 a0 = make_float4(0.f, 0.f, 0.f, 0.f), a1 = a0, a2 = a0, a3 = a0;
    float  d = 0.f;

    if (cnt > 0) {
        const float4* r = (const float4*)(xb + (size_t)s_list[0] * ROW);
        float4 c0 = __ldg(r + lane),      c1 = __ldg(r + lane + 32),
               c2 = __ldg(r + lane + 64), c3 = __ldg(r + lane + 96);

        for (int i = 0; i < cnt; ++i) {
            // prefetch next row
            float4 n0 = c0, n1 = c1, n2 = c2, n3 = c3;
            if (i + 1 < cnt) {
                const float4* rn = (const float4*)(xb + (size_t)s_list[i + 1] * ROW);
                n0 = __ldg(rn + lane);      n1 = __ldg(rn + lane + 32);
                n2 = __ldg(rn + lane + 64); n3 = __ldg(rn + lane + 96);
            }

            // score (warp reduce)
            float p = c0.x * wv.x + c0.y * wv.y + c0.z * wv.z + c0.w * wv.w;
            p      += c1.x * wv.x + c1.y * wv.y + c1.z * wv.z + c1.w * wv.w;
            p      += c2.x * wv.x + c2.y * wv.y + c2.z * wv.z + c2.w * wv.w;
            p      += c3.x * wv.x + c3.y * wv.y + c3.z * wv.z + c3.w * wv.w;
            #pragma unroll
            for (int off = 16; off; off >>= 1)
                p += __shfl_xor_sync(0xFFFFFFFFu, p, off);

            const float e = __expf(p * 0.125f + bv);   // |arg| small: safe
            d += e;
            a0.x = fmaf(e, c0.x, a0.x); a0.y = fmaf(e, c0.y, a0.y);
            a0.z = fmaf(e, c0.z, a0.z); a0.w = fmaf(e, c0.w, a0.w);
            a1.x = fmaf(e, c1.x, a1.x); a1.y = fmaf(e, c1.y, a1.y);
            a1.z = fmaf(e, c1.z, a1.z); a1.w = fmaf(e, c1.w, a1.w);
            a2.x = fmaf(e, c2.x, a2.x); a2.y = fmaf(e, c2.y, a2.y);
            a2.z = fmaf(e, c2.z, a2.z); a2.w = fmaf(e, c2.w, a2.w);
            a3.x = fmaf(e, c3.x, a3.x); a3.y = fmaf(e, c3.y, a3.y);
            a3.z = fmaf(e, c3.z, a3.z); a3.w = fmaf(e, c3.w, a3.w);

            c0 = n0; c1 = n1; c2 = n2; c3 = n3;
        }
    }

    const float inv = (cnt > 0) ? (1.f / d) : 0.f;
    a0.x *= inv; a0.y *= inv; a0.z *= inv; a0.w *= inv;
    a1.x *= inv; a1.y *= inv; a1.z *= inv; a1.w *= inv;
    a2.x *= inv; a2.y *= inv; a2.z *= inv; a2.w *= inv;
    a3.x *= inv; a3.y *= inv; a3.z *= inv; a3.w *= inv;

    float4* o = (float4*)out + (size_t)(b * CC + c) * (ROW / 4);
    o[lane]      = a0;
    o[lane + 32] = a1;
    o[lane + 64] = a2;
    o[lane + 96] = a3;
}

extern "C" void kernel_launch(void* const* d_in, const int* in_sizes, int n_in,
                              void* d_out, int out_size) {
    const float* x    = (const float*)d_in[0];
    const float* W    = (const float*)d_in[1];
    const float* bias = (const float*)d_in[2];
    const int*   seg  = (const int*)d_in[3];

    build_lists_kernel<<<CC, 128>>>(seg);
    pool_kernel<<<4096, 32>>>(x, W, bias, (float*)d_out);
}

// round 9
// speedup vs baseline: 1.1362x; 1.0631x over previous
#include <cuda_runtime.h>
#include <cstdint>
#include <float.h>

// GraphPooling: B=16, N=4096, F=8, H=64, C=256
// out[b,c,:,:] = sum_{n: seg[n]==c} softmax_w(b,n) * x[b,n,:,:]
// score[b,n] = dot(x_row, W_rep)/F + bias ; softmax per (b, segment).
// Warp-per-item; rows streamed through a per-warp cp.async smem ring (depth 3)
// so MLP lives in smem, not registers. No max-subtraction (|score| <~ 2 << 88).

#define BB   16
#define NN   4096
#define CC   256
#define ROW  512
#define MAXPER 96
#define STAGES 4

__device__ int g_list[CC * MAXPER];
__device__ int g_cnt[CC];

// Block c compacts segment c. Thread t owns chunk [t*32, t*32+32):
// concatenated order = increasing node index (deterministic).
__global__ __launch_bounds__(128) void build_lists_kernel(const int* __restrict__ seg) {
    __shared__ int s_seg[NN];
    __shared__ int s_cnt[128];
    __shared__ int s_wtot[4];

    const int c    = blockIdx.x;
    const int tid  = threadIdx.x;
    const int lane = tid & 31;
    const int wid  = tid >> 5;

    for (int i = tid; i < NN / 4; i += 128)
        ((int4*)s_seg)[i] = ((const int4*)seg)[i];
    __syncthreads();

    const int base = tid * 32;
    int cnt = 0;
    #pragma unroll
    for (int j = 0; j < 32; ++j) cnt += (s_seg[base + j] == c);

    int incl = cnt;
    #pragma unroll
    for (int off = 1; off < 32; off <<= 1) {
        const int v = __shfl_up_sync(0xFFFFFFFFu, incl, off);
        if (lane >= off) incl += v;
    }
    if (lane == 31) s_wtot[wid] = incl;
    s_cnt[tid] = incl - cnt;
    __syncthreads();
    int wbase = 0;
    #pragma unroll
    for (int w = 0; w < 4; ++w) { if (w < wid) wbase += s_wtot[w]; }
    const int offset = s_cnt[tid] + wbase;

    if (tid == 127) {
        const int total = offset + cnt;
        g_cnt[c] = total < MAXPER ? total : MAXPER;
    }

    int p = offset;
    #pragma unroll
    for (int j = 0; j < 32; ++j) {
        if (s_seg[base + j] == c) {
            if (p < MAXPER) g_list[c * MAXPER + p] = base + j;
            ++p;
        }
    }
}

__device__ __forceinline__ void cp16(unsigned int dst, const void* src) {
    asm volatile("cp.async.cg.shared.global [%0], [%1], 16;\n"
                 :: "r"(dst), "l"(src) : "memory");
}
__device__ __forceinline__ void cp_commit() {
    asm volatile("cp.async.commit_group;\n" ::: "memory");
}
__device__ __forceinline__ void cp_wait3() {
    asm volatile("cp.async.wait_group 3;\n" ::: "memory");
}

// Issue row k of the list into ring stage st (always commits, so group
// counting stays aligned even past the end of the list).
__device__ __forceinline__ void issue_row(const float* xb, const int* myl,
                                          int k, int cnt, int st,
                                          unsigned int sbase, int lane) {
    if (k < cnt) {
        const char* s = (const char*)(xb + (size_t)myl[k] * ROW) + (size_t)lane * 16u;
        const unsigned int d = sbase + (unsigned int)st * 2048u;
        cp16(d,         s);
        cp16(d + 512u,  s + 512);
        cp16(d + 1024u, s + 1024);
        cp16(d + 1536u, s + 1536);
    }
    cp_commit();
}

// 1024 CTAs x 128 threads; warp handles item = blockIdx.x*4 + wid.
// b = item & 15, c = item >> 4. Lane owns row float4 slots {lane, +32, +64, +96}.
__global__ __launch_bounds__(128) void pool_kernel(
    const float* __restrict__ x,
    const float* __restrict__ W,
    const float* __restrict__ bias,
    float* __restrict__ out)
{
    __shared__ float4 s_buf[4][STAGES][128];   // 4 warps x 4 stages x 2KB = 32KB
    __shared__ int    s_list[4][MAXPER];

    const int lane = threadIdx.x & 31;
    const int wid  = threadIdx.x >> 5;
    const int item = blockIdx.x * 4 + wid;
    const int b    = item & 15;
    const int c    = item >> 4;

    const int cnt = g_cnt[c];
    int* myl = s_list[wid];
    for (int i = lane; i < cnt; i += 32) myl[i] = g_list[c * MAXPER + i];
    __syncwarp();

    const float4 wv = *(const float4*)(W + ((lane * 4) & 63));
    const float  bv = __ldg(bias);
    const float* xb = x + (size_t)b * NN * ROW;

    const unsigned int sbase =
        (unsigned int)__cvta_generic_to_shared(&s_buf[wid][0][0]) + (unsigned int)lane * 16u;

    float4 a0 = make_float4(0.f, 0.f, 0.f, 0.f), a1 = a0, a2 = a0, a3 = a0;
    float  d = 0.f;

    if (cnt > 0) {
        issue_row(xb, myl, 0, cnt, 0, sbase, lane);
        issue_row(xb, myl, 1, cnt, 1, sbase, lane);
        issue_row(xb, myl, 2, cnt, 2, sbase, lane);

        for (int i = 0; i < cnt; ++i) {
            issue_row(xb, myl, i + 3, cnt, (i + 3) & 3, sbase, lane);
            cp_wait3();                        // row i resident
            const int st = i & 3;
            const float4 c0 = s_buf[wid][st][lane];
            const float4 c1 = s_buf[wid][st][lane + 32];
            const float4 c2 = s_buf[wid][st][lane + 64];
            const float4 c3 = s_buf[wid][st][lane + 96];

            float p = c0.x * wv.x + c0.y * wv.y + c0.z * wv.z + c0.w * wv.w;
            p      += c1.x * wv.x + c1.y * wv.y + c1.z * wv.z + c1.w * wv.w;
            p      += c2.x * wv.x + c2.y * wv.y + c2.z * wv.z + c2.w * wv.w;
            p      += c3.x * wv.x + c3.y * wv.y + c3.z * wv.z + c3.w * wv.w;
            #pragma unroll
            for (int off = 16; off; off >>= 1)
                p += __shfl_xor_sync(0xFFFFFFFFu, p, off);

            const float e = __expf(p * 0.125f + bv);   // |arg| small: no rescale
            d += e;
            a0.x = fmaf(e, c0.x, a0.x); a0.y = fmaf(e, c0.y, a0.y);
            a0.z = fmaf(e, c0.z, a0.z); a0.w = fmaf(e, c0.w, a0.w);
            a1.x = fmaf(e, c1.x, a1.x); a1.y = fmaf(e, c1.y, a1.y);
            a1.z = fmaf(e, c1.z, a1.z); a1.w = fmaf(e, c1.w, a1.w);
            a2.x = fmaf(e, c2.x, a2.x); a2.y = fmaf(e, c2.y, a2.y);
            a2.z = fmaf(e, c2.z, a2.z); a2.w = fmaf(e, c2.w, a2.w);
            a3.x = fmaf(e, c3.x, a3.x); a3.y = fmaf(e, c3.y, a3.y);
            a3.z = fmaf(e, c3.z, a3.z); a3.w = fmaf(e, c3.w, a3.w);
        }
    }

    const float inv = (cnt > 0) ? (1.f / d) : 0.f;
    a0.x *= inv; a0.y *= inv; a0.z *= inv; a0.w *= inv;
    a1.x *= inv; a1.y *= inv; a1.z *= inv; a1.w *= inv;
    a2.x *= inv; a2.y *= inv; a2.z *= inv; a2.w *= inv;
    a3.x *= inv; a3.y *= inv; a3.z *= inv; a3.w *= inv;

    float4* o = (float4*)out + (size_t)(b * CC + c) * (ROW / 4);
    o[lane]      = a0;
    o[lane + 32] = a1;
    o[lane + 64] = a2;
    o[lane + 96] = a3;
}

extern "C" void kernel_launch(void* const* d_in, const int* in_sizes, int n_in,
                              void* d_out, int out_size) {
    const float* x    = (const float*)d_in[0];
    const float* W    = (const float*)d_in[1];
    const float* bias = (const float*)d_in[2];
    const int*   seg  = (const int*)d_in[3];

    build_lists_kernel<<<CC, 128>>>(seg);
    pool_kernel<<<1024, 128>>>(x, W, bias, (float*)d_out);
}

// round 10
// speedup vs baseline: 1.2620x; 1.1107x over previous
#include <cuda_runtime.h>
#include <cstdint>
#include <float.h>

// GraphPooling: B=16, N=4096, F=8, H=64, C=256
// out[b,c,:,:] = sum_{n: seg[n]==c} softmax_w(b,n) * x[b,n,:,:]
// score[b,n] = dot(x_row, W_rep)/F + bias ; softmax per (b, segment).
// Warp-per-item, cp.async smem ring, rows processed in PAIRS with interleaved
// warp reductions (two independent shuffle chains overlap).
// No max-subtraction (|score| <~ 2 << 88: exp(s)/sum == exp(s-m)/sum(exp(s-m))).

#define BB   16
#define NN   4096
#define CC   256
#define ROW  512
#define MAXPER 96
#define STAGES 4

__device__ int g_list[CC * MAXPER];
__device__ int g_cnt[CC];

// Block c compacts segment c. Thread t owns chunk [t*16, t*16+16):
// concatenated order = increasing node index (deterministic).
__global__ __launch_bounds__(256) void build_lists_kernel(const int* __restrict__ seg) {
    __shared__ int s_seg[NN];
    __shared__ int s_cnt[256];
    __shared__ int s_wtot[8];

    const int c    = blockIdx.x;
    const int tid  = threadIdx.x;
    const int lane = tid & 31;
    const int wid  = tid >> 5;

    for (int i = tid; i < NN / 4; i += 256)
        ((int4*)s_seg)[i] = ((const int4*)seg)[i];
    __syncthreads();

    const int base = tid * 16;
    int cnt = 0;
    #pragma unroll
    for (int j = 0; j < 16; ++j) cnt += (s_seg[base + j] == c);

    int incl = cnt;
    #pragma unroll
    for (int off = 1; off < 32; off <<= 1) {
        const int v = __shfl_up_sync(0xFFFFFFFFu, incl, off);
        if (lane >= off) incl += v;
    }
    if (lane == 31) s_wtot[wid] = incl;
    s_cnt[tid] = incl - cnt;
    __syncthreads();
    int wbase = 0;
    #pragma unroll
    for (int w = 0; w < 8; ++w) { if (w < wid) wbase += s_wtot[w]; }
    const int offset = s_cnt[tid] + wbase;

    if (tid == 255) {
        const int total = offset + cnt;
        g_cnt[c] = total < MAXPER ? total : MAXPER;
    }

    int p = offset;
    #pragma unroll
    for (int j = 0; j < 16; ++j) {
        if (s_seg[base + j] == c) {
            if (p < MAXPER) g_list[c * MAXPER + p] = base + j;
            ++p;
        }
    }
}

__device__ __forceinline__ void cp16(unsigned int dst, const void* src) {
    asm volatile("cp.async.cg.shared.global [%0], [%1], 16;\n"
                 :: "r"(dst), "l"(src) : "memory");
}
__device__ __forceinline__ void cp_commit() {
    asm volatile("cp.async.commit_group;\n" ::: "memory");
}
__device__ __forceinline__ void cp_wait2() {
    asm volatile("cp.async.wait_group 2;\n" ::: "memory");
}
__device__ __forceinline__ void cp_wait0() {
    asm volatile("cp.async.wait_group 0;\n" ::: "memory");
}

// Issue row k into ring stage k&3 (always commits -> exact group counting).
__device__ __forceinline__ void issue_row(const float* xb, const int* myl,
                                          int k, int cnt,
                                          unsigned int sbase, int lane) {
    if (k < cnt) {
        const char* s = (const char*)(xb + (size_t)myl[k] * ROW) + (size_t)lane * 16u;
        const unsigned int d = sbase + (unsigned int)(k & 3) * 2048u;
        cp16(d,         s);
        cp16(d + 512u,  s + 512);
        cp16(d + 1024u, s + 1024);
        cp16(d + 1536u, s + 1536);
    }
    cp_commit();
}

// 1024 CTAs x 128 threads; warp handles item = blockIdx.x*4 + wid.
// b = item & 15, c = item >> 4. Lane owns row float4 slots {lane, +32, +64, +96}.
__global__ __launch_bounds__(128) void pool_kernel(
    const float* __restrict__ x,
    const float* __restrict__ W,
    const float* __restrict__ bias,
    float* __restrict__ out)
{
    __shared__ float4 s_buf[4][STAGES][128];   // 4 warps x 4 row-stages x 2KB = 32KB
    __shared__ int    s_list[4][MAXPER];

    const int lane = threadIdx.x & 31;
    const int wid  = threadIdx.x >> 5;
    const int item = blockIdx.x * 4 + wid;
    const int b    = item & 15;
    const int c    = item >> 4;

    const int cnt = g_cnt[c];
    int* myl = s_list[wid];
    for (int i = lane; i < cnt; i += 32) myl[i] = g_list[c * MAXPER + i];
    __syncwarp();

    const float4 wv = *(const float4*)(W + ((lane * 4) & 63));
    const float  bv = __ldg(bias);
    const float* xb = x + (size_t)b * NN * ROW;

    const unsigned int sbase =
        (unsigned int)__cvta_generic_to_shared(&s_buf[wid][0][0]) + (unsigned int)lane * 16u;

    float4 a0 = make_float4(0.f, 0.f, 0.f, 0.f), a1 = a0, a2 = a0, a3 = a0;
    float  d = 0.f;

    if (cnt > 0) {
        issue_row(xb, myl, 0, cnt, sbase, lane);
        issue_row(xb, myl, 1, cnt, sbase, lane);
        issue_row(xb, myl, 2, cnt, sbase, lane);
        issue_row(xb, myl, 3, cnt, sbase, lane);

        int i = 0;
        for (; i + 1 < cnt; i += 2) {
            cp_wait2();                         // rows i, i+1 resident
            const int stA = i & 3, stB = (i + 1) & 3;
            const float4 A0 = s_buf[wid][stA][lane];
            const float4 A1 = s_buf[wid][stA][lane + 32];
            const float4 A2 = s_buf[wid][stA][lane + 64];
            const float4 A3 = s_buf[wid][stA][lane + 96];
            const float4 B0 = s_buf[wid][stB][lane];
            const float4 B1 = s_buf[wid][stB][lane + 32];
            const float4 B2 = s_buf[wid][stB][lane + 64];
            const float4 B3 = s_buf[wid][stB][lane + 96];

            float pa = A0.x * wv.x + A0.y * wv.y + A0.z * wv.z + A0.w * wv.w;
            pa      += A1.x * wv.x + A1.y * wv.y + A1.z * wv.z + A1.w * wv.w;
            pa      += A2.x * wv.x + A2.y * wv.y + A2.z * wv.z + A2.w * wv.w;
            pa      += A3.x * wv.x + A3.y * wv.y + A3.z * wv.z + A3.w * wv.w;
            float pb = B0.x * wv.x + B0.y * wv.y + B0.z * wv.z + B0.w * wv.w;
            pb      += B1.x * wv.x + B1.y * wv.y + B1.z * wv.z + B1.w * wv.w;
            pb      += B2.x * wv.x + B2.y * wv.y + B2.z * wv.z + B2.w * wv.w;
            pb      += B3.x * wv.x + B3.y * wv.y + B3.z * wv.z + B3.w * wv.w;

            #pragma unroll
            for (int off = 16; off; off >>= 1) {   // two independent chains interleave
                pa += __shfl_xor_sync(0xFFFFFFFFu, pa, off);
                pb += __shfl_xor_sync(0xFFFFFFFFu, pb, off);
            }

            const float ea = __expf(pa * 0.125f + bv);
            const float eb = __expf(pb * 0.125f + bv);

            d += ea;                                // fold A (list order)
            a0.x = fmaf(ea, A0.x, a0.x); a0.y = fmaf(ea, A0.y, a0.y);
            a0.z = fmaf(ea, A0.z, a0.z); a0.w = fmaf(ea, A0.w, a0.w);
            a1.x = fmaf(ea, A1.x, a1.x); a1.y = fmaf(ea, A1.y, a1.y);
            a1.z = fmaf(ea, A1.z, a1.z); a1.w = fmaf(ea, A1.w, a1.w);
            a2.x = fmaf(ea, A2.x, a2.x); a2.y = fmaf(ea, A2.y, a2.y);
            a2.z = fmaf(ea, A2.z, a2.z); a2.w = fmaf(ea, A2.w, a2.w);
            a3.x = fmaf(ea, A3.x, a3.x); a3.y = fmaf(ea, A3.y, a3.y);
            a3.z = fmaf(ea, A3.z, a3.z); a3.w = fmaf(ea, A3.w, a3.w);

            d += eb;                                // fold B
            a0.x = fmaf(eb, B0.x, a0.x); a0.y = fmaf(eb, B0.y, a0.y);
            a0.z = fmaf(eb, B0.z, a0.z); a0.w = fmaf(eb, B0.w, a0.w);
            a1.x = fmaf(eb, B1.x, a1.x); a1.y = fmaf(eb, B1.y, a1.y);
            a1.z = fmaf(eb, B1.z, a1.z); a1.w = fmaf(eb, B1.w, a1.w);
            a2.x = fmaf(eb, B2.x, a2.x); a2.y = fmaf(eb, B2.y, a2.y);
            a2.z = fmaf(eb, B2.z, a2.z); a2.w = fmaf(eb, B2.w, a2.w);
            a3.x = fmaf(eb, B3.x, a3.x); a3.y = fmaf(eb, B3.y, a3.y);
            a3.z = fmaf(eb, B3.z, a3.z); a3.w = fmaf(eb, B3.w, a3.w);

            // refill the two stages just consumed
            issue_row(xb, myl, i + 4, cnt, sbase, lane);
            issue_row(xb, myl, i + 5, cnt, sbase, lane);
        }

        if (i < cnt) {                              // odd tail (single row)
            cp_wait0();
            const int st = i & 3;
            const float4 C0 = s_buf[wid][st][lane];
            const float4 C1 = s_buf[wid][st][lane + 32];
            const float4 C2 = s_buf[wid][st][lane + 64];
            const float4 C3 = s_buf[wid][st][lane + 96];

            float p = C0.x * wv.x + C0.y * wv.y + C0.z * wv.z + C0.w * wv.w;
            p      += C1.x * wv.x + C1.y * wv.y + C1.z * wv.z + C1.w * wv.w;
            p      += C2.x * wv.x + C2.y * wv.y + C2.z * wv.z + C2.w * wv.w;
            p      += C3.x * wv.x + C3.y * wv.y + C3.z * wv.z + C3.w * wv.w;
            #pragma unroll
            for (int off = 16; off; off >>= 1)
                p += __shfl_xor_sync(0xFFFFFFFFu, p, off);

            const float e = __expf(p * 0.125f + bv);
            d += e;
            a0.x = fmaf(e, C0.x, a0.x); a0.y = fmaf(e, C0.y, a0.y);
            a0.z = fmaf(e, C0.z, a0.z); a0.w = fmaf(e, C0.w, a0.w);
            a1.x = fmaf(e, C1.x, a1.x); a1.y = fmaf(e, C1.y, a1.y);
            a1.z = fmaf(e, C1.z, a1.z); a1.w = fmaf(e, C1.w, a1.w);
            a2.x = fmaf(e, C2.x, a2.x); a2.y = fmaf(e, C2.y, a2.y);
            a2.z = fmaf(e, C2.z, a2.z); a2.w = fmaf(e, C2.w, a2.w);
            a3.x = fmaf(e, C3.x, a3.x); a3.y = fmaf(e, C3.y, a3.y);
            a3.z = fmaf(e, C3.z, a3.z); a3.w = fmaf(e, C3.w, a3.w);
        }
    }

    const float inv = (cnt > 0) ? (1.f / d) : 0.f;
    a0.x *= inv; a0.y *= inv; a0.z *= inv; a0.w *= inv;
    a1.x *= inv; a1.y *= inv; a1.z *= inv; a1.w *= inv;
    a2.x *= inv; a2.y *= inv; a2.z *= inv; a2.w *= inv;
    a3.x *= inv; a3.y *= inv; a3.z *= inv; a3.w *= inv;

    float4* o = (float4*)out + (size_t)(b * CC + c) * (ROW / 4);
    o[lane]      = a0;
    o[lane + 32] = a1;
    o[lane + 64] = a2;
    o[lane + 96] = a3;
}

extern "C" void kernel_launch(void* const* d_in, const int* in_sizes, int n_in,
                              void* d_out, int out_size) {
    const float* x    = (const float*)d_in[0];
    const float* W    = (const float*)d_in[1];
    const float* bias = (const float*)d_in[2];
    const int*   seg  = (const int*)d_in[3];

    build_lists_kernel<<<CC, 256>>>(seg);
    pool_kernel<<<1024, 128>>>(x, W, bias, (float*)d_out);
}

// round 11
// speedup vs baseline: 1.3167x; 1.0433x over previous
#include <cuda_runtime.h>
#include <cstdint>
#include <float.h>

// GraphPooling: B=16, N=4096, F=8, H=64, C=256
// out[b,c,:,:] = sum_{n: seg[n]==c} softmax_w(b,n) * x[b,n,:,:]
// score[b,n] = dot(x_row, W_rep)/F + bias ; softmax per (b, segment).
// Items split across WARP PAIRS (strided halves; partials merge by addition
// since no max-subtraction is needed: |score| <~ 2 << 88). cp.async smem ring.

#define BB   16
#define NN   4096
#define CC   256
#define ROW  512
#define MAXPER 96
#define STAGES 4

__device__ int g_list[CC * MAXPER];
__device__ int g_cnt[CC];

// Block c compacts segment c. Thread t owns chunk [t*16, t*16+16):
// concatenated order = increasing node index (deterministic).
__global__ __launch_bounds__(256) void build_lists_kernel(const int* __restrict__ seg) {
    __shared__ int s_seg[NN];
    __shared__ int s_cnt[256];
    __shared__ int s_wtot[8];

    const int c    = blockIdx.x;
    const int tid  = threadIdx.x;
    const int lane = tid & 31;
    const int wid  = tid >> 5;

    for (int i = tid; i < NN / 4; i += 256)
        ((int4*)s_seg)[i] = ((const int4*)seg)[i];
    __syncthreads();

    const int base = tid * 16;
    int cnt = 0;
    #pragma unroll
    for (int j = 0; j < 16; ++j) cnt += (s_seg[base + j] == c);

    int incl = cnt;
    #pragma unroll
    for (int off = 1; off < 32; off <<= 1) {
        const int v = __shfl_up_sync(0xFFFFFFFFu, incl, off);
        if (lane >= off) incl += v;
    }
    if (lane == 31) s_wtot[wid] = incl;
    s_cnt[tid] = incl - cnt;
    __syncthreads();
    int wbase = 0;
    #pragma unroll
    for (int w = 0; w < 8; ++w) { if (w < wid) wbase += s_wtot[w]; }
    const int offset = s_cnt[tid] + wbase;

    if (tid == 255) {
        const int total = offset + cnt;
        g_cnt[c] = total < MAXPER ? total : MAXPER;
    }

    int p = offset;
    #pragma unroll
    for (int j = 0; j < 16; ++j) {
        if (s_seg[base + j] == c) {
            if (p < MAXPER) g_list[c * MAXPER + p] = base + j;
            ++p;
        }
    }
}

__device__ __forceinline__ void cp16(unsigned int dst, const void* src) {
    asm volatile("cp.async.cg.shared.global [%0], [%1], 16;\n"
                 :: "r"(dst), "l"(src) : "memory");
}
__device__ __forceinline__ void cp_commit() {
    asm volatile("cp.async.commit_group;\n" ::: "memory");
}
__device__ __forceinline__ void cp_wait2() {
    asm volatile("cp.async.wait_group 2;\n" ::: "memory");
}
__device__ __forceinline__ void cp_wait0() {
    asm volatile("cp.async.wait_group 0;\n" ::: "memory");
}
__device__ __forceinline__ void pair_bar(int id) {
    asm volatile("bar.sync %0, %1;" :: "r"(id), "r"(64) : "memory");
}

// Issue k-th row of this half (global list row half + 2k) into stage k&3.
// Always commits -> exact group counting.
__device__ __forceinline__ void issue_row(const float* xb, const int* myl,
                                          int half, int k, int cnt_h,
                                          unsigned int sbase, int lane) {
    if (k < cnt_h) {
        const char* s = (const char*)(xb + (size_t)myl[half + (k << 1)] * ROW)
                      + (size_t)lane * 16u;
        const unsigned int d = sbase + (unsigned int)(k & 3) * 2048u;
        cp16(d,         s);
        cp16(d + 512u,  s + 512);
        cp16(d + 1024u, s + 1024);
        cp16(d + 1536u, s + 1536);
    }
    cp_commit();
}

// 2048 CTAs x 128 threads (4 warps = 2 pairs). Pair p = wid>>1 owns
// item = blockIdx.x*2 + p; warp half = wid&1 processes rows half, half+2, ...
// Lane owns row float4 slots {lane, +32, +64, +96}.
__global__ __launch_bounds__(128) void pool_kernel(
    const float* __restrict__ x,
    const float* __restrict__ W,
    const float* __restrict__ bias,
    float* __restrict__ out)
{
    __shared__ float4 s_buf[4][STAGES][128];   // 32 KB: ring, then partial staging
    __shared__ int    s_list[2][MAXPER];
    __shared__ float  s_d[4];

    const int lane = threadIdx.x & 31;
    const int wid  = threadIdx.x >> 5;
    const int pair = wid >> 1;
    const int half = wid & 1;
    const int item = blockIdx.x * 2 + pair;
    const int b    = item & 15;
    const int c    = item >> 4;

    const int cnt = g_cnt[c];
    int* myl = s_list[pair];
    for (int i = lane; i < cnt; i += 32) myl[i] = g_list[c * MAXPER + i];
    __syncwarp();   // both warps of the pair write identical values; own writes visible

    const int cnt_h = (cnt > half) ? ((cnt - half + 1) >> 1) : 0;

    const float4 wv = *(const float4*)(W + ((lane * 4) & 63));
    const float  bv = __ldg(bias);
    const float* xb = x + (size_t)b * NN * ROW;

    const unsigned int sbase =
        (unsigned int)__cvta_generic_to_shared(&s_buf[wid][0][0]) + (unsigned int)lane * 16u;

    float4 a0 = make_float4(0.f, 0.f, 0.f, 0.f), a1 = a0, a2 = a0, a3 = a0;
    float  d = 0.f;

    if (cnt_h > 0) {
        issue_row(xb, myl, half, 0, cnt_h, sbase, lane);
        issue_row(xb, myl, half, 1, cnt_h, sbase, lane);
        issue_row(xb, myl, half, 2, cnt_h, sbase, lane);
        issue_row(xb, myl, half, 3, cnt_h, sbase, lane);

        int i = 0;
        for (; i + 1 < cnt_h; i += 2) {
            cp_wait2();                         // rows i, i+1 of this half resident
            const int stA = i & 3, stB = (i + 1) & 3;
            const float4 A0 = s_buf[wid][stA][lane];
            const float4 A1 = s_buf[wid][stA][lane + 32];
            const float4 A2 = s_buf[wid][stA][lane + 64];
            const float4 A3 = s_buf[wid][stA][lane + 96];
            const float4 B0 = s_buf[wid][stB][lane];
            const float4 B1 = s_buf[wid][stB][lane + 32];
            const float4 B2 = s_buf[wid][stB][lane + 64];
            const float4 B3 = s_buf[wid][stB][lane + 96];

            float pa = A0.x * wv.x + A0.y * wv.y + A0.z * wv.z + A0.w * wv.w;
            pa      += A1.x * wv.x + A1.y * wv.y + A1.z * wv.z + A1.w * wv.w;
            pa      += A2.x * wv.x + A2.y * wv.y + A2.z * wv.z + A2.w * wv.w;
            pa      += A3.x * wv.x + A3.y * wv.y + A3.z * wv.z + A3.w * wv.w;
            float pb = B0.x * wv.x + B0.y * wv.y + B0.z * wv.z + B0.w * wv.w;
            pb      += B1.x * wv.x + B1.y * wv.y + B1.z * wv.z + B1.w * wv.w;
            pb      += B2.x * wv.x + B2.y * wv.y + B2.z * wv.z + B2.w * wv.w;
            pb      += B3.x * wv.x + B3.y * wv.y + B3.z * wv.z + B3.w * wv.w;

            #pragma unroll
            for (int off = 16; off; off >>= 1) {
                pa += __shfl_xor_sync(0xFFFFFFFFu, pa, off);
                pb += __shfl_xor_sync(0xFFFFFFFFu, pb, off);
            }

            const float ea = __expf(pa * 0.125f + bv);
            const float eb = __expf(pb * 0.125f + bv);

            d += ea;
            a0.x = fmaf(ea, A0.x, a0.x); a0.y = fmaf(ea, A0.y, a0.y);
            a0.z = fmaf(ea, A0.z, a0.z); a0.w = fmaf(ea, A0.w, a0.w);
            a1.x = fmaf(ea, A1.x, a1.x); a1.y = fmaf(ea, A1.y, a1.y);
            a1.z = fmaf(ea, A1.z, a1.z); a1.w = fmaf(ea, A1.w, a1.w);
            a2.x = fmaf(ea, A2.x, a2.x); a2.y = fmaf(ea, A2.y, a2.y);
            a2.z = fmaf(ea, A2.z, a2.z); a2.w = fmaf(ea, A2.w, a2.w);
            a3.x = fmaf(ea, A3.x, a3.x); a3.y = fmaf(ea, A3.y, a3.y);
            a3.z = fmaf(ea, A3.z, a3.z); a3.w = fmaf(ea, A3.w, a3.w);

            d += eb;
            a0.x = fmaf(eb, B0.x, a0.x); a0.y = fmaf(eb, B0.y, a0.y);
            a0.z = fmaf(eb, B0.z, a0.z); a0.w = fmaf(eb, B0.w, a0.w);
            a1.x = fmaf(eb, B1.x, a1.x); a1.y = fmaf(eb, B1.y, a1.y);
            a1.z = fmaf(eb, B1.z, a1.z); a1.w = fmaf(eb, B1.w, a1.w);
            a2.x = fmaf(eb, B2.x, a2.x); a2.y = fmaf(eb, B2.y, a2.y);
            a2.z = fmaf(eb, B2.z, a2.z); a2.w = fmaf(eb, B2.w, a2.w);
            a3.x = fmaf(eb, B3.x, a3.x); a3.y = fmaf(eb, B3.y, a3.y);
            a3.z = fmaf(eb, B3.z, a3.z); a3.w = fmaf(eb, B3.w, a3.w);

            issue_row(xb, myl, half, i + 4, cnt_h, sbase, lane);
            issue_row(xb, myl, half, i + 5, cnt_h, sbase, lane);
        }

        if (i < cnt_h) {                        // odd tail
            cp_wait0();
            const int st = i & 3;
            const float4 C0 = s_buf[wid][st][lane];
            const float4 C1 = s_buf[wid][st][lane + 32];
            const float4 C2 = s_buf[wid][st][lane + 64];
            const float4 C3 = s_buf[wid][st][lane + 96];

            float p = C0.x * wv.x + C0.y * wv.y + C0.z * wv.z + C0.w * wv.w;
            p      += C1.x * wv.x + C1.y * wv.y + C1.z * wv.z + C1.w * wv.w;
            p      += C2.x * wv.x + C2.y * wv.y + C2.z * wv.z + C2.w * wv.w;
            p      += C3.x * wv.x + C3.y * wv.y + C3.z * wv.z + C3.w * wv.w;
            #pragma unroll
            for (int off = 16; off; off >>= 1)
                p += __shfl_xor_sync(0xFFFFFFFFu, p, off);

            const float e = __expf(p * 0.125f + bv);
            d += e;
            a0.x = fmaf(e, C0.x, a0.x); a0.y = fmaf(e, C0.y, a0.y);
            a0.z = fmaf(e, C0.z, a0.z); a0.w = fmaf(e, C0.w, a0.w);
            a1.x = fmaf(e, C1.x, a1.x); a1.y = fmaf(e, C1.y, a1.y);
            a1.z = fmaf(e, C1.z, a1.z); a1.w = fmaf(e, C1.w, a1.w);
            a2.x = fmaf(e, C2.x, a2.x); a2.y = fmaf(e, C2.y, a2.y);
            a2.z = fmaf(e, C2.z, a2.z); a2.w = fmaf(e, C2.w, a2.w);
            a3.x = fmaf(e, C3.x, a3.x); a3.y = fmaf(e, C3.y, a3.y);
            a3.z = fmaf(e, C3.z, a3.z); a3.w = fmaf(e, C3.w, a3.w);
        }
    }
    cp_wait0();   // drain any remaining (empty) groups before reusing the ring

    // stage partials in own ring stage 0; merge within the pair (fixed order).
    s_buf[wid][0][lane]      = a0;
    s_buf[wid][0][lane + 32] = a1;
    s_buf[wid][0][lane + 64] = a2;
    s_buf[wid][0][lane + 96] = a3;
    if (lane == 0) s_d[wid] = d;
    pair_bar(pair + 1);

    if (half == 0) {
        const int pw = wid + 1;                 // partner warp
        const float D = s_d[wid] + s_d[pw];     // even + odd, fixed order
        const float inv = (cnt > 0) ? (1.f / D) : 0.f;

        float4 o0 = s_buf[pw][0][lane];
        float4 o1 = s_buf[pw][0][lane + 32];
        float4 o2 = s_buf[pw][0][lane + 64];
        float4 o3 = s_buf[pw][0][lane + 96];
        o0.x = (a0.x + o0.x) * inv; o0.y = (a0.y + o0.y) * inv;
        o0.z = (a0.z + o0.z) * inv; o0.w = (a0.w + o0.w) * inv;
        o1.x = (a1.x + o1.x) * inv; o1.y = (a1.y + o1.y) * inv;
        o1.z = (a1.z + o1.z) * inv; o1.w = (a1.w + o1.w) * inv;
        o2.x = (a2.x + o2.x) * inv; o2.y = (a2.y + o2.y) * inv;
        o2.z = (a2.z + o2.z) * inv; o2.w = (a2.w + o2.w) * inv;
        o3.x = (a3.x + o3.x) * inv; o3.y = (a3.y + o3.y) * inv;
        o3.z = (a3.z + o3.z) * inv; o3.w = (a3.w + o3.w) * inv;

        float4* o = (float4*)out + (size_t)(b * CC + c) * (ROW / 4);
        o[lane]      = o0;
        o[lane + 32] = o1;
        o[lane + 64] = o2;
        o[lane + 96] = o3;
    }
}

extern "C" void kernel_launch(void* const* d_in, const int* in_sizes, int n_in,
                              void* d_out, int out_size) {
    const float* x    = (const float*)d_in[0];
    const float* W    = (const float*)d_in[1];
    const float* bias = (const float*)d_in[2];
    const int*   seg  = (const int*)d_in[3];

    build_lists_kernel<<<CC, 256>>>(seg);
    pool_kernel<<<2048, 128>>>(x, W, bias, (float*)d_out);
}

// round 13
// speedup vs baseline: 1.3333x; 1.0127x over previous
#include <cuda_runtime.h>
#include <cstdint>
#include <float.h>

// GraphPooling: B=16, N=4096, F=8, H=64, C=256
// out[b,c,:,:] = sum_{n: seg[n]==c} softmax_w(b,n) * x[b,n,:,:]
// score[b,n] = dot(x_row, W_rep)/F + bias ; softmax per (b, segment).
// One 64-thread CTA (warp pair) per item; each warp streams a strided half of
// the segment list through a private 4-stage cp.async ring (distance-3 prefetch).
// No max-subtraction (|score| <~ 2 << 88): partials merge by plain addition.

#define BB   16
#define NN   4096
#define CC   256
#define ROW  512
#define MAXPER 96
#define STAGES 4

__device__ int g_list[CC * MAXPER];
__device__ int g_cnt[CC];

// Block c compacts segment c. Thread t owns chunk [t*16, t*16+16):
// concatenated order = increasing node index (deterministic).
__global__ __launch_bounds__(256) void build_lists_kernel(const int* __restrict__ seg) {
    __shared__ int s_seg[NN];
    __shared__ int s_cnt[256];
    __shared__ int s_wtot[8];

    const int c    = blockIdx.x;
    const int tid  = threadIdx.x;
    const int lane = tid & 31;
    const int wid  = tid >> 5;

    for (int i = tid; i < NN / 4; i += 256)
        ((int4*)s_seg)[i] = ((const int4*)seg)[i];
    __syncthreads();

    const int base = tid * 16;
    int cnt = 0;
    #pragma unroll
    for (int j = 0; j < 16; ++j) cnt += (s_seg[base + j] == c);

    int incl = cnt;
    #pragma unroll
    for (int off = 1; off < 32; off <<= 1) {
        const int v = __shfl_up_sync(0xFFFFFFFFu, incl, off);
        if (lane >= off) incl += v;
    }
    if (lane == 31) s_wtot[wid] = incl;
    s_cnt[tid] = incl - cnt;
    __syncthreads();
    int wbase = 0;
    #pragma unroll
    for (int w = 0; w < 8; ++w) { if (w < wid) wbase += s_wtot[w]; }
    const int offset = s_cnt[tid] + wbase;

    if (tid == 255) {
        const int total = offset + cnt;
        g_cnt[c] = total < MAXPER ? total : MAXPER;
    }

    int p = offset;
    #pragma unroll
    for (int j = 0; j < 16; ++j) {
        if (s_seg[base + j] == c) {
            if (p < MAXPER) g_list[c * MAXPER + p] = base + j;
            ++p;
        }
    }
}

__device__ __forceinline__ void cp16(unsigned int dst, const void* src) {
    asm volatile("cp.async.cg.shared.global [%0], [%1], 16;\n"
                 :: "r"(dst), "l"(src) : "memory");
}
__device__ __forceinline__ void cp_commit() {
    asm volatile("cp.async.commit_group;\n" ::: "memory");
}
__device__ __forceinline__ void cp_wait3() {
    asm volatile("cp.async.wait_group 3;\n" ::: "memory");
}
__device__ __forceinline__ void cp_wait0() {
    asm volatile("cp.async.wait_group 0;\n" ::: "memory");
}

// Issue k-th row of this half (global list row half + 2k) into stage k&3.
// Always commits -> exact group counting.
__device__ __forceinline__ void issue_row(const float* xb, const int* myl,
                                          int half, int k, int cnt_h,
                                          unsigned int sbase, int lane) {
    if (k < cnt_h) {
        const char* s = (const char*)(xb + (size_t)myl[half + (k << 1)] * ROW)
                      + (size_t)lane * 16u;
        const unsigned int d = sbase + (unsigned int)(k & 3) * 2048u;
        cp16(d,         s);
        cp16(d + 512u,  s + 512);
        cp16(d + 1024u, s + 1024);
        cp16(d + 1536u, s + 1536);
    }
    cp_commit();
}

// 4096 CTAs x 64 threads (one warp pair). CTA handles item = blockIdx.x:
// b = item & 15, c = item >> 4. Warp half = wid processes list rows half, half+2, ...
// Lane owns row float4 slots {lane, +32, +64, +96}.
__global__ __launch_bounds__(64) void pool_kernel(
    const float* __restrict__ x,
    const float* __restrict__ W,
    const float* __restrict__ bias,
    float* __restrict__ out)
{
    __shared__ float4 s_buf[2][STAGES][128];   // 16 KB: ring, then partial staging
    __shared__ int    s_list[MAXPER];
    __shared__ float  s_d[2];

    const int lane = threadIdx.x & 31;
    const int half = threadIdx.x >> 5;         // warp id within pair
    const int item = blockIdx.x;
    const int b    = item & 15;
    const int c    = item >> 4;

    const int cnt = g_cnt[c];
    for (int i = lane; i < cnt; i += 32) s_list[i] = g_list[c * MAXPER + i];
    __syncwarp();   // both warps write identical values; own writes visible

    const int cnt_h = (cnt > half) ? ((cnt - half + 1) >> 1) : 0;

    const float4 wv = *(const float4*)(W + ((lane * 4) & 63));
    const float  bv = __ldg(bias);
    const float* xb = x + (size_t)b * NN * ROW;

    const unsigned int sbase =
        (unsigned int)__cvta_generic_to_shared(&s_buf[half][0][0]) + (unsigned int)lane * 16u;

    float4 a0 = make_float4(0.f, 0.f, 0.f, 0.f), a1 = a0, a2 = a0, a3 = a0;
    float  d = 0.f;

    if (cnt_h > 0) {
        issue_row(xb, s_list, half, 0, cnt_h, sbase, lane);
        issue_row(xb, s_list, half, 1, cnt_h, sbase, lane);
        issue_row(xb, s_list, half, 2, cnt_h, sbase, lane);

        for (int i = 0; i < cnt_h; ++i) {
            issue_row(xb, s_list, half, i + 3, cnt_h, sbase, lane);
            cp_wait3();                        // row i of this half resident
            const int st = i & 3;
            const float4 c0 = s_buf[half][st][lane];
            const float4 c1 = s_buf[half][st][lane + 32];
            const float4 c2 = s_buf[half][st][lane + 64];
            const float4 c3 = s_buf[half][st][lane + 96];

            float p = c0.x * wv.x + c0.y * wv.y + c0.z * wv.z + c0.w * wv.w;
            p      += c1.x * wv.x + c1.y * wv.y + c1.z * wv.z + c1.w * wv.w;
            p      += c2.x * wv.x + c2.y * wv.y + c2.z * wv.z + c2.w * wv.w;
            p      += c3.x * wv.x + c3.y * wv.y + c3.z * wv.z + c3.w * wv.w;
            #pragma unroll
            for (int off = 16; off; off >>= 1)
                p += __shfl_xor_sync(0xFFFFFFFFu, p, off);

            const float e = __expf(p * 0.125f + bv);   // |arg| small: no rescale
            d += e;
            a0.x = fmaf(e, c0.x, a0.x); a0.y = fmaf(e, c0.y, a0.y);
            a0.z = fmaf(e, c0.z, a0.z); a0.w = fmaf(e, c0.w, a0.w);
            a1.x = fmaf(e, c1.x, a1.x); a1.y = fmaf(e, c1.y, a1.y);
            a1.z = fmaf(e, c1.z, a1.z); a1.w = fmaf(e, c1.w, a1.w);
            a2.x = fmaf(e, c2.x, a2.x); a2.y = fmaf(e, c2.y, a2.y);
            a2.z = fmaf(e, c2.z, a2.z); a2.w = fmaf(e, c2.w, a2.w);
            a3.x = fmaf(e, c3.x, a3.x); a3.y = fmaf(e, c3.y, a3.y);
            a3.z = fmaf(e, c3.z, a3.z); a3.w = fmaf(e, c3.w, a3.w);
        }
    }
    cp_wait0();   // drain remaining (possibly empty) groups before ring reuse

    // stage this warp's partials in its ring stage 0; merge within the pair.
    s_buf[half][0][lane]      = a0;
    s_buf[half][0][lane + 32] = a1;
    s_buf[half][0][lane + 64] = a2;
    s_buf[half][0][lane + 96] = a3;
    if (lane == 0) s_d[half] = d;
    __syncthreads();

    if (half == 0) {
        const float D   = s_d[0] + s_d[1];      // even + odd halves, fixed order
        const float inv = (cnt > 0) ? (1.f / D) : 0.f;

        float4 o0 = s_buf[1][0][lane];
        float4 o1 = s_buf[1][0][lane + 32];
        float4 o2 = s_buf[1][0][lane + 64];
        float4 o3 = s_buf[1][0][lane + 96];
        o0.x = (a0.x + o0.x) * inv; o0.y = (a0.y + o0.y) * inv;
        o0.z = (a0.z + o0.z) * inv; o0.w = (a0.w + o0.w) * inv;
        o1.x = (a1.x + o1.x) * inv; o1.y = (a1.y + o1.y) * inv;
        o1.z = (a1.z + o1.z) * inv; o1.w = (a1.w + o1.w) * inv;
        o2.x = (a2.x + o2.x) * inv; o2.y = (a2.y + o2.y) * inv;
        o2.z = (a2.z + o2.z) * inv; o2.w = (a2.w + o2.w) * inv;
        o3.x = (a3.x + o3.x) * inv; o3.y = (a3.y + o3.y) * inv;
        o3.z = (a3.z + o3.z) * inv; o3.w = (a3.w + o3.w) * inv;

        float4* o = (float4*)out + (size_t)(b * CC + c) * (ROW / 4);
        o[lane]      = o0;
        o[lane + 32] = o1;
        o[lane + 64] = o2;
        o[lane + 96] = o3;
    }
}

extern "C" void kernel_launch(void* const* d_in, const int* in_sizes, int n_in,
                              void* d_out, int out_size) {
    const float* x    = (const float*)d_in[0];
    const float* W    = (const float*)d_in[1];
    const float* bias = (const float*)d_in[2];
    const int*   seg  = (const int*)d_in[3];

    build_lists_kernel<<<CC, 256>>>(seg);
    pool_kernel<<<4096, 64>>>(x, W, bias, (float*)d_out);
}